// round 11
// baseline (speedup 1.0000x reference)
#include <cuda_runtime.h>
#include <cuda_bf16.h>
#include <math.h>
#include <stdint.h>

// Problem constants (fixed by dataset)
#define T_STEPS 2000
#define B_SZ    64
#define H_SZ    512
#define G4      2048
#define NCTA    128

typedef unsigned long long ull;

// ---------------------------------------------------------------------------
// Device scratch (no allocations allowed anywhere)
// ---------------------------------------------------------------------------
__device__ float        g_s[H_SZ];                   // gate vector s[H]
__device__ unsigned int g_flag[4 * 256];             // per (bg, ug) publish flags, 32B padded
__device__ float        g_h[4][B_SZ * H_SZ];         // h ring buffer (L2-resident)

// ---------------------------------------------------------------------------
// Packed f32x2 helpers (PTX-only)
// ---------------------------------------------------------------------------
__device__ __forceinline__ void fma2(ull& d, ull a, ull b) {
    asm("fma.rn.f32x2 %0, %1, %2, %0;" : "+l"(d) : "l"(a), "l"(b));
}
__device__ __forceinline__ void unpack2(ull v, float& x, float& y) {
    asm("mov.b64 {%0,%1}, %2;" : "=f"(x), "=f"(y) : "l"(v));
}
__device__ __forceinline__ ull pack2(float x, float y) {
    ull v;
    asm("mov.b64 %0, {%1,%2};" : "=l"(v) : "f"(x), "f"(y));
    return v;
}
__device__ __forceinline__ float sigf(float x) {
    return __fdividef(1.0f, 1.0f + __expf(-x));
}
// accurate fast tanh: (e^{2x}-1)/(e^{2x}+1), clamped (tanh saturates anyway)
__device__ __forceinline__ float tanhx(float x) {
    float xc = fminf(fmaxf(x, -15.0f), 15.0f);
    float e  = __expf(2.0f * xc);
    return __fdividef(e - 1.0f, e + 1.0f);
}

// ---------------------------------------------------------------------------
// Prep: s = clip(sigmoid(log_alpha)*1.2 - 0.1, 0, 1); zero h0; reset flags
// ---------------------------------------------------------------------------
__global__ void prep_kernel(const float* __restrict__ la) {
    int t = threadIdx.x;  // 512 threads
    float v = 1.0f / (1.0f + expf(-la[t]));
    v = v * 1.2f - 0.1f;
    v = fminf(fmaxf(v, 0.0f), 1.0f);
    g_s[t] = v;
    for (int i = t; i < B_SZ * H_SZ; i += 512) g_h[0][i] = 0.0f;
    if (t < 4 * 256) g_flag[t] = 0u;
}

// no-op spacers so the fixed `ncu -s 5 -c 1` lands on lstm_kernel (slot 5)
__global__ void spacer_kernel() { }

// ---------------------------------------------------------------------------
// Fused persistent kernel:
// 128 CTAs = 4 batch-groups (16 b) x 32 unit-groups (16 u).
// Per step: dot1 = h_t . U_hat (U in SMEM); combine with gxr regs (gx[t]);
// publish h_{t+1}; then dot2 = (x[t+1].s) . W (W streamed from L2) -> gxr.
// Dataflow sync via per-(bg, ug) monotone flags; 4-deep h ring (skew-1 safe).
// ---------------------------------------------------------------------------
#define SHS 516                     // h/x row stride (16B-aligned rows)
#define SUS 516                     // U row stride
#define SRS 17                      // reduce buffer row stride (2-way max on write)
#define U_F   (64 * SUS)            // 33024
#define H_F   (16 * SHS)            // 8256
#define R_F   (8 * 64 * SRS)        // 8704
#define S_F   512
#define LSMEM_FLOATS (U_F + H_F + R_F + S_F + 32)

// load operand set (a-matrix rows from h_s region) for 4-k iteration kp
#define LOADX(xv, kp)                                                           \
    do {                                                                        \
        _Pragma("unroll")                                                       \
        for (int bb = 0; bb < 4; ++bb)                                          \
            xv[bb] = *(const ulonglong2*)&h_s[(bb * 4 + bq) * SHS + kbase + 4 * (kp)]; \
    } while (0)

#define LOADU(uv, kp)                                                           \
    do {                                                                        \
        _Pragma("unroll")                                                       \
        for (int rr = 0; rr < 8; ++rr)                                          \
            uv[rr] = *(const ulonglong2*)&U_s[(rr * 8 + rq) * SUS + kbase + 4 * (kp)]; \
    } while (0)

#define LOADW(wv, kp)                                                           \
    do {                                                                        \
        _Pragma("unroll")                                                       \
        for (int rr = 0; rr < 8; ++rr)                                          \
            wv[rr] = __ldg((const ulonglong2*)(wrow[rr] + 4 * (kp)));           \
    } while (0)

// x-pass then y-pass: each acc touched twice, 32 instructions apart
#define FMASET(hv, uv)                                                          \
    do {                                                                        \
        _Pragma("unroll")                                                       \
        for (int bb = 0; bb < 4; ++bb)                                          \
            _Pragma("unroll")                                                   \
            for (int rr = 0; rr < 8; ++rr)                                      \
                fma2(acc[bb][rr], hv[bb].x, uv[rr].x);                          \
        _Pragma("unroll")                                                       \
        for (int bb = 0; bb < 4; ++bb)                                          \
            _Pragma("unroll")                                                   \
            for (int rr = 0; rr < 8; ++rr)                                      \
                fma2(acc[bb][rr], hv[bb].y, uv[rr].y);                          \
    } while (0)

#define REDWRITE()                                                              \
    do {                                                                        \
        _Pragma("unroll")                                                       \
        for (int bb = 0; bb < 4; ++bb)                                          \
            _Pragma("unroll")                                                   \
            for (int rr = 0; rr < 8; ++rr) {                                    \
                float x, y;                                                     \
                unpack2(acc[bb][rr], x, y);                                     \
                red[(warp * 64 + rr * 8 + rq) * SRS + bb * 4 + bq] = x + y;     \
            }                                                                   \
    } while (0)

__global__ void __launch_bounds__(256, 1)
lstm_kernel(const float* __restrict__ X, const float* __restrict__ U,
            const float* __restrict__ W, const float* __restrict__ bias,
            float* __restrict__ out) {
    extern __shared__ float sm[];
    float* U_s = sm;
    float* h_s = sm + U_F;
    float* red = sm + U_F + H_F;
    float* s_s = sm + U_F + H_F + R_F;

    int tid  = threadIdx.x;
    int warp = tid >> 5;
    int lane = tid & 31;

    int ug = blockIdx.x >> 2;       // 0..31
    int bg = blockIdx.x & 3;        // 0..3
    int u0 = ug * 16;
    int b0 = bg * 16;

    unsigned int* myflag = &g_flag[bg * 256 + ug * 8];
    const unsigned int* wflag = &g_flag[bg * 256 + warp * 32 + (lane & 3) * 8];

    // ---- copy s to smem
    for (int i = tid; i < 512; i += 256) s_s[i] = g_s[i];

    // ---- load U_hat slice once: row lr = gate*16 + u_local
    for (int i = 0; i < 128; ++i) {
        int idx = i * 256 + tid;            // 0..32767
        int lr  = idx >> 9;
        int k   = idx & 511;
        int gg  = lr >> 4;
        int uu  = lr & 15;
        float v = U[((size_t)(gg * 512 + u0 + uu)) * 512 + k] * g_s[u0 + uu] * g_s[k];
        U_s[lr * SUS + k] = v;
    }

    // dot-phase lane ids: batches b = bb*4 + bq, rows lr = rr*8 + rq
    int rq    = lane & 7;
    int bq    = lane >> 3;
    int kbase = warp * 64;

    // per-warp stage ids: lane covers b = lane&15, half = lane>>4
    int sb    = lane & 15;
    int shalf = lane >> 4;

    // combine-phase ids (one (b, u) cell per thread; u contiguous in lane)
    int cb = tid >> 4;              // 0..15
    int cu = tid & 15;              // 0..15
    float c_state = 0.0f;

    // per-lane W row pointers (constant across steps)
    const float* wrow[8];
#pragma unroll
    for (int rr = 0; rr < 8; ++rr) {
        int lr = rr * 8 + rq;
        wrow[rr] = W + ((size_t)((lr >> 4) * 512 + u0 + (lr & 15))) * 512 + kbase;
    }

    // per-thread bias (4 gates of cell (cb, cu))
    float bias_r[4];
#pragma unroll
    for (int g = 0; g < 4; ++g) bias_r[g] = bias[g * 512 + u0 + cu];

    float gxr[4];                   // gx for MY cell at the upcoming step

    __syncthreads();

    // ---- gemm for step tt -> gxr (stages x into h_s warp region; uses red)
    auto gemm_step = [&](int tt) {
        // stage x[tt] slice scaled by s (warp-private h_s region)
        {
            const ull* src = (const ull*)(X + ((size_t)tt * 64 + b0) * 512);
#pragma unroll
            for (int j = 0; j < 16; ++j) {
                int c2 = warp * 32 + 2 * j + shalf;        // ull index in row
                ull v = __ldcg(&src[sb * 256 + c2]);
                float lo, hi;
                unpack2(v, lo, hi);
                lo *= s_s[2 * c2];
                hi *= s_s[2 * c2 + 1];
                *(ull*)&h_s[sb * SHS + kbase + 4 * j + 2 * shalf] = pack2(lo, hi);
            }
        }
        __syncwarp();

        ull acc[4][8];
#pragma unroll
        for (int i = 0; i < 4; ++i)
#pragma unroll
            for (int j = 0; j < 8; ++j) acc[i][j] = 0ull;

        {
            ulonglong2 wva[8], wvb[8], xva[4], xvb[4];
            LOADW(wva, 0);
#pragma unroll
            for (int kp = 0; kp < 16; kp += 2) {
                LOADW(wvb, kp + 1);
                LOADX(xva, kp);
                FMASET(xva, wva);
                if (kp < 14) LOADW(wva, kp + 2);
                LOADX(xvb, kp + 1);
                FMASET(xvb, wvb);
            }
        }

        REDWRITE();
        __syncthreads();                       // S3: red2 ready

#pragma unroll
        for (int g = 0; g < 4; ++g) {
            float z = bias_r[g];
#pragma unroll
            for (int w = 0; w < 8; ++w)
                z += red[(w * 64 + g * 16 + cu) * SRS + cb];
            gxr[g] = z;
        }
        __syncthreads();                       // S4: red2 consumed
    };

    gemm_step(0);                              // gx for t = 0

    for (int t = 0; t < T_STEPS; ++t) {
        const float* hin  = g_h[t & 3];
        float*       hout = g_h[(t + 1) & 3];

        // ---- wait for this warp's 4 producer unit-groups (h_t published)
        {
            unsigned v;
            do {
                asm volatile("ld.relaxed.gpu.u32 %0, [%1];"
                             : "=r"(v) : "l"(wflag));
            } while (__any_sync(0xffffffffu, (int)v < t));
            asm volatile("fence.acquire.gpu;" ::: "memory");
        }

        // ---- per-warp h stage: this warp's 16 b x 64 k slice (4 KB), CF banks
        {
            const ull* src = (const ull*)(hin + (size_t)b0 * 512);
#pragma unroll
            for (int j = 0; j < 16; ++j) {
                ull v = __ldcg(&src[sb * 256 + warp * 32 + 2 * j + shalf]);
                *(ull*)&h_s[sb * SHS + kbase + 4 * j + 2 * shalf] = v;
            }
        }
        __syncwarp();

        // ---- dot1: h . U_hat (2-stage pipelined, x/y-split FMA passes)
        ull acc[4][8];
#pragma unroll
        for (int i = 0; i < 4; ++i)
#pragma unroll
            for (int j = 0; j < 8; ++j) acc[i][j] = 0ull;

        {
            ulonglong2 hva[4], uva[8], hvb[4], uvb[8];
            LOADX(hva, 0);
            LOADU(uva, 0);
#pragma unroll
            for (int kp2 = 0; kp2 < 8; ++kp2) {
                LOADX(hvb, 2 * kp2 + 1);
                LOADU(uvb, 2 * kp2 + 1);
                FMASET(hva, uva);
                if (kp2 < 7) {
                    LOADX(hva, 2 * kp2 + 2);
                    LOADU(uva, 2 * kp2 + 2);
                }
                FMASET(hvb, uvb);
            }
        }

        REDWRITE();
        __syncthreads();                       // S1: red1 ready

        // ---- fused reduce + combine: one (b, u) cell per thread
        float z0 = gxr[0], z1 = gxr[1], z2 = gxr[2], z3 = gxr[3];
#pragma unroll
        for (int w = 0; w < 8; ++w) {
            z0 += red[(w * 64 +  0 + cu) * SRS + cb];
            z1 += red[(w * 64 + 16 + cu) * SRS + cb];
            z2 += red[(w * 64 + 32 + cu) * SRS + cb];
            z3 += red[(w * 64 + 48 + cu) * SRS + cb];
        }
        float ig = sigf(z0);
        float fg = sigf(z1);
        float gg = tanhx(z2);
        float og = sigf(z3);
        float cn = fg * c_state + ig * gg;
        c_state  = cn;
        float hn = og * tanhx(cn);

        // h exchange store (L2) must precede the publish
        hout[(b0 + cb) * 512 + u0 + cu] = hn;

        __syncthreads();                       // S2: hout stores + red1 reads done
        if (tid == 0) {
            asm volatile("fence.acq_rel.gpu;" ::: "memory");
            asm volatile("st.release.gpu.u32 [%0], %1;"
                         :: "l"(myflag), "r"(t + 1) : "memory");
        }

        // DRAM output store overlaps peers' publication
        out[((size_t)t * 64 + b0 + cb) * 512 + u0 + cu] = hn;

        // ---- gemm for step t+1 (fills idle pipes while peers publish)
        if (t + 1 < T_STEPS) gemm_step(t + 1);
    }
}

// ---------------------------------------------------------------------------
extern "C" void kernel_launch(void* const* d_in, const int* in_sizes, int n_in,
                              void* d_out, int out_size) {
    const float* x  = (const float*)d_in[0];
    const float* W  = (const float*)d_in[1];
    const float* U  = (const float*)d_in[2];
    const float* b  = (const float*)d_in[3];
    const float* la = (const float*)d_in[4];
    float* out = (float*)d_out;

    prep_kernel<<<1, 512>>>(la);
    spacer_kernel<<<1, 32>>>();
    spacer_kernel<<<1, 32>>>();   // keep 4 launches/call: ncu slot 5 = lstm

    cudaFuncSetAttribute(lstm_kernel, cudaFuncAttributeMaxDynamicSharedMemorySize,
                         LSMEM_FLOATS * 4);
    lstm_kernel<<<NCTA, 256, LSMEM_FLOATS * 4>>>(x, U, W, b, out);
}

// round 12
// speedup vs baseline: 1.3882x; 1.3882x over previous
#include <cuda_runtime.h>
#include <cuda_bf16.h>
#include <math.h>
#include <stdint.h>

// Problem constants (fixed by dataset)
#define T_STEPS 2000
#define B_SZ    64
#define H_SZ    512
#define G4      2048
#define NCTA    128

typedef unsigned long long ull;

// ---------------------------------------------------------------------------
// Device scratch (no allocations allowed anywhere)
// ---------------------------------------------------------------------------
__device__ float        g_s[H_SZ];                   // gate vector s[H]
__device__ unsigned int g_flag[4 * 256];             // per (bg, ug) publish flags, 32B padded
__device__ float        g_h[4][B_SZ * H_SZ];         // h ring buffer (L2-resident)

// ---------------------------------------------------------------------------
// Packed f32x2 helpers (PTX-only)
// ---------------------------------------------------------------------------
__device__ __forceinline__ void fma2(ull& d, ull a, ull b) {
    asm("fma.rn.f32x2 %0, %1, %2, %0;" : "+l"(d) : "l"(a), "l"(b));
}
__device__ __forceinline__ void unpack2(ull v, float& x, float& y) {
    asm("mov.b64 {%0,%1}, %2;" : "=f"(x), "=f"(y) : "l"(v));
}
__device__ __forceinline__ ull pack2(float x, float y) {
    ull v;
    asm("mov.b64 %0, {%1,%2};" : "=l"(v) : "f"(x), "f"(y));
    return v;
}
__device__ __forceinline__ float sigf(float x) {
    return __fdividef(1.0f, 1.0f + __expf(-x));
}
// accurate fast tanh: (e^{2x}-1)/(e^{2x}+1), clamped (tanh saturates anyway)
__device__ __forceinline__ float tanhx(float x) {
    float xc = fminf(fmaxf(x, -15.0f), 15.0f);
    float e  = __expf(2.0f * xc);
    return __fdividef(e - 1.0f, e + 1.0f);
}

// ---------------------------------------------------------------------------
// Prep: s = clip(sigmoid(log_alpha)*1.2 - 0.1, 0, 1); zero h0; reset flags
// ---------------------------------------------------------------------------
__global__ void prep_kernel(const float* __restrict__ la) {
    int t = threadIdx.x;  // 512 threads
    float v = 1.0f / (1.0f + expf(-la[t]));
    v = v * 1.2f - 0.1f;
    v = fminf(fmaxf(v, 0.0f), 1.0f);
    g_s[t] = v;
    for (int i = t; i < B_SZ * H_SZ; i += 512) g_h[0][i] = 0.0f;
    if (t < 4 * 256) g_flag[t] = 0u;
}

// no-op spacers so the fixed `ncu -s 5 -c 1` lands on lstm_kernel (slot 5)
__global__ void spacer_kernel() { }

// ---------------------------------------------------------------------------
// Fused persistent kernel:
// 128 CTAs = 4 batch-groups (16 b) x 32 unit-groups (16 u).
// Per step: dot1 = h_t . U_hat (U in SMEM, mapping A: 4b x 8r per lane);
// combine with gxr regs; publish h_{t+1}; then dot2 = (x[t+1].s) . W
// (W streamed from L2, mapping B: 8b x 4r per lane -> low reg pressure).
// Dataflow sync via per-(bg, ug) monotone flags; 4-deep h ring (skew-1 safe).
// ---------------------------------------------------------------------------
#define SHS 516                     // h/x row stride (16B-aligned rows)
#define SUS 516                     // U row stride
#define SRS 17                      // reduce buffer row stride
#define U_F   (64 * SUS)            // 33024
#define H_F   (16 * SHS)            // 8256
#define R_F   (8 * 64 * SRS)        // 8704
#define S_F   512
#define LSMEM_FLOATS (U_F + H_F + R_F + S_F + 32)

// ---- mapping A (dot1) --------------------------------------------------
#define LOADX(xv, kp)                                                           \
    do {                                                                        \
        _Pragma("unroll")                                                       \
        for (int bb = 0; bb < 4; ++bb)                                          \
            xv[bb] = *(const ulonglong2*)&h_s[(bb * 4 + bq) * SHS + kbase + 4 * (kp)]; \
    } while (0)

#define LOADU(uv, kp)                                                           \
    do {                                                                        \
        _Pragma("unroll")                                                       \
        for (int rr = 0; rr < 8; ++rr)                                          \
            uv[rr] = *(const ulonglong2*)&U_s[(rr * 8 + rq) * SUS + kbase + 4 * (kp)]; \
    } while (0)

#define FMASET(hv, uv)                                                          \
    do {                                                                        \
        _Pragma("unroll")                                                       \
        for (int bb = 0; bb < 4; ++bb)                                          \
            _Pragma("unroll")                                                   \
            for (int rr = 0; rr < 8; ++rr)                                      \
                fma2(acc[bb][rr], hv[bb].x, uv[rr].x);                          \
        _Pragma("unroll")                                                       \
        for (int bb = 0; bb < 4; ++bb)                                          \
            _Pragma("unroll")                                                   \
            for (int rr = 0; rr < 8; ++rr)                                      \
                fma2(acc[bb][rr], hv[bb].y, uv[rr].y);                          \
    } while (0)

#define REDWRITE()                                                              \
    do {                                                                        \
        _Pragma("unroll")                                                       \
        for (int bb = 0; bb < 4; ++bb)                                          \
            _Pragma("unroll")                                                   \
            for (int rr = 0; rr < 8; ++rr) {                                    \
                float x, y;                                                     \
                unpack2(acc[bb][rr], x, y);                                     \
                red[(warp * 64 + rr * 8 + rq) * SRS + bb * 4 + bq] = x + y;     \
            }                                                                   \
    } while (0)

// ---- mapping B (gemm dot2): lane = (rq16 row-slot, bq2 batch-slot) -----
// row = rr*16 + rq16  (rr == gate), batch = bb*2 + bq2
#define LOADXB(xv, kp)                                                          \
    do {                                                                        \
        _Pragma("unroll")                                                       \
        for (int bb = 0; bb < 8; ++bb)                                          \
            xv[bb] = *(const ulonglong2*)&h_s[(bb * 2 + bq2) * SHS + kbase + 4 * (kp)]; \
    } while (0)

#define LOADWB(wv, kp)                                                          \
    do {                                                                        \
        _Pragma("unroll")                                                       \
        for (int rr = 0; rr < 4; ++rr)                                          \
            wv[rr] = __ldg((const ulonglong2*)(wbase + rr * 262144 + 4 * (kp))); \
    } while (0)

#define FMAB(xv, wv)                                                            \
    do {                                                                        \
        _Pragma("unroll")                                                       \
        for (int bb = 0; bb < 8; ++bb)                                          \
            _Pragma("unroll")                                                   \
            for (int rr = 0; rr < 4; ++rr)                                      \
                fma2(accg[bb][rr], xv[bb].x, wv[rr].x);                         \
        _Pragma("unroll")                                                       \
        for (int bb = 0; bb < 8; ++bb)                                          \
            _Pragma("unroll")                                                   \
            for (int rr = 0; rr < 4; ++rr)                                      \
                fma2(accg[bb][rr], xv[bb].y, wv[rr].y);                         \
    } while (0)

#define REDWRITEB()                                                             \
    do {                                                                        \
        _Pragma("unroll")                                                       \
        for (int bb = 0; bb < 8; ++bb)                                          \
            _Pragma("unroll")                                                   \
            for (int rr = 0; rr < 4; ++rr) {                                    \
                float x, y;                                                     \
                unpack2(accg[bb][rr], x, y);                                    \
                red[(warp * 64 + rr * 16 + rq16) * SRS + bb * 2 + bq2] = x + y; \
            }                                                                   \
    } while (0)

__global__ void __launch_bounds__(256, 1)
lstm_kernel(const float* __restrict__ X, const float* __restrict__ U,
            const float* __restrict__ W, const float* __restrict__ bias,
            float* __restrict__ out) {
    extern __shared__ float sm[];
    float* U_s = sm;
    float* h_s = sm + U_F;
    float* red = sm + U_F + H_F;
    float* s_s = sm + U_F + H_F + R_F;

    int tid  = threadIdx.x;
    int warp = tid >> 5;
    int lane = tid & 31;

    int ug = blockIdx.x >> 2;       // 0..31
    int bg = blockIdx.x & 3;        // 0..3
    int u0 = ug * 16;
    int b0 = bg * 16;

    unsigned int* myflag = &g_flag[bg * 256 + ug * 8];
    const unsigned int* wflag = &g_flag[bg * 256 + warp * 32 + (lane & 3) * 8];

    // ---- copy s to smem
    for (int i = tid; i < 512; i += 256) s_s[i] = g_s[i];

    // ---- load U_hat slice once: row lr = gate*16 + u_local
    for (int i = 0; i < 128; ++i) {
        int idx = i * 256 + tid;            // 0..32767
        int lr  = idx >> 9;
        int k   = idx & 511;
        int gg  = lr >> 4;
        int uu  = lr & 15;
        float v = U[((size_t)(gg * 512 + u0 + uu)) * 512 + k] * g_s[u0 + uu] * g_s[k];
        U_s[lr * SUS + k] = v;
    }

    // mapping A lane ids
    int rq    = lane & 7;
    int bq    = lane >> 3;
    int kbase = warp * 64;

    // mapping B lane ids
    int rq16 = lane & 15;
    int bq2  = lane >> 4;
    const float* wbase = W + ((size_t)(u0 + rq16)) * 512 + kbase;

    // per-warp stage ids: lane covers b = lane&15, half = lane>>4
    int sb    = lane & 15;
    int shalf = lane >> 4;

    // combine-phase ids (one (b, u) cell per thread; u contiguous in lane)
    int cb = tid >> 4;              // 0..15
    int cu = tid & 15;              // 0..15
    float c_state = 0.0f;

    // per-thread bias (4 gates of cell (cb, cu))
    float bias_r[4];
#pragma unroll
    for (int g = 0; g < 4; ++g) bias_r[g] = bias[g * 512 + u0 + cu];

    float gxr[4];                   // gx for MY cell at the upcoming step

    __syncthreads();

    // ---- gemm for step tt -> gxr (stages x into h_s warp region; uses red)
    auto gemm_step = [&](int tt) {
        // stage x[tt] slice scaled by s (warp-private h_s column region)
        {
            const ull* src = (const ull*)(X + ((size_t)tt * 64 + b0) * 512);
#pragma unroll
            for (int j = 0; j < 16; ++j) {
                int c2 = warp * 32 + 2 * j + shalf;        // ull index in row
                ull v = __ldcg(&src[sb * 256 + c2]);
                float lo, hi;
                unpack2(v, lo, hi);
                lo *= s_s[2 * c2];
                hi *= s_s[2 * c2 + 1];
                *(ull*)&h_s[sb * SHS + kbase + 4 * j + 2 * shalf] = pack2(lo, hi);
            }
        }
        __syncwarp();

        ull accg[8][4];
#pragma unroll
        for (int i = 0; i < 8; ++i)
#pragma unroll
            for (int j = 0; j < 4; ++j) accg[i][j] = 0ull;

        {
            ulonglong2 wa[4], wb[4], wc[4], wd[4], xv[8];
            LOADWB(wa, 0);
            LOADWB(wb, 1);
            LOADWB(wc, 2);
#pragma unroll
            for (int kp = 0; kp < 16; kp += 4) {
                LOADWB(wd, kp + 3);
                LOADXB(xv, kp);
                FMAB(xv, wa);
                if (kp < 12) LOADWB(wa, kp + 4);
                LOADXB(xv, kp + 1);
                FMAB(xv, wb);
                if (kp < 12) LOADWB(wb, kp + 5);
                LOADXB(xv, kp + 2);
                FMAB(xv, wc);
                if (kp < 12) LOADWB(wc, kp + 6);
                LOADXB(xv, kp + 3);
                FMAB(xv, wd);
            }
        }

        REDWRITEB();
        __syncthreads();                       // S3: red2 ready

#pragma unroll
        for (int g = 0; g < 4; ++g) {
            float z = bias_r[g];
#pragma unroll
            for (int w = 0; w < 8; ++w)
                z += red[(w * 64 + g * 16 + cu) * SRS + cb];
            gxr[g] = z;
        }
        __syncthreads();                       // S4: red2 consumed
    };

    gemm_step(0);                              // gx for t = 0

    for (int t = 0; t < T_STEPS; ++t) {
        const float* hin  = g_h[t & 3];
        float*       hout = g_h[(t + 1) & 3];

        // ---- wait for this warp's 4 producer unit-groups (h_t published)
        {
            unsigned v;
            do {
                asm volatile("ld.relaxed.gpu.u32 %0, [%1];"
                             : "=r"(v) : "l"(wflag));
            } while (__any_sync(0xffffffffu, (int)v < t));
            asm volatile("fence.acquire.gpu;" ::: "memory");
        }

        // ---- per-warp h stage: this warp's 16 b x 64 k slice (4 KB), CF banks
        {
            const ull* src = (const ull*)(hin + (size_t)b0 * 512);
#pragma unroll
            for (int j = 0; j < 16; ++j) {
                ull v = __ldcg(&src[sb * 256 + warp * 32 + 2 * j + shalf]);
                *(ull*)&h_s[sb * SHS + kbase + 4 * j + 2 * shalf] = v;
            }
        }
        __syncwarp();

        // ---- dot1: h . U_hat (2-stage pipelined, x/y-split FMA passes)
        ull acc[4][8];
#pragma unroll
        for (int i = 0; i < 4; ++i)
#pragma unroll
            for (int j = 0; j < 8; ++j) acc[i][j] = 0ull;

        {
            ulonglong2 hva[4], uva[8], hvb[4], uvb[8];
            LOADX(hva, 0);
            LOADU(uva, 0);
#pragma unroll
            for (int kp2 = 0; kp2 < 8; ++kp2) {
                LOADX(hvb, 2 * kp2 + 1);
                LOADU(uvb, 2 * kp2 + 1);
                FMASET(hva, uva);
                if (kp2 < 7) {
                    LOADX(hva, 2 * kp2 + 2);
                    LOADU(uva, 2 * kp2 + 2);
                }
                FMASET(hvb, uvb);
            }
        }

        REDWRITE();
        __syncthreads();                       // S1: red1 ready

        // ---- fused reduce + combine: one (b, u) cell per thread
        float z0 = gxr[0], z1 = gxr[1], z2 = gxr[2], z3 = gxr[3];
#pragma unroll
        for (int w = 0; w < 8; ++w) {
            z0 += red[(w * 64 +  0 + cu) * SRS + cb];
            z1 += red[(w * 64 + 16 + cu) * SRS + cb];
            z2 += red[(w * 64 + 32 + cu) * SRS + cb];
            z3 += red[(w * 64 + 48 + cu) * SRS + cb];
        }
        float ig = sigf(z0);
        float fg = sigf(z1);
        float gg = tanhx(z2);
        float og = sigf(z3);
        float cn = fg * c_state + ig * gg;
        c_state  = cn;
        float hn = og * tanhx(cn);

        // h exchange store (L2) must precede the publish
        hout[(b0 + cb) * 512 + u0 + cu] = hn;

        __syncthreads();                       // S2: hout stores + red1 reads done
        if (tid == 0) {
            asm volatile("fence.acq_rel.gpu;" ::: "memory");
            asm volatile("st.release.gpu.u32 [%0], %1;"
                         :: "l"(myflag), "r"(t + 1) : "memory");
        }

        // DRAM output store overlaps peers' publication
        out[((size_t)t * 64 + b0 + cb) * 512 + u0 + cu] = hn;

        // ---- gemm for step t+1 (fills idle pipes while peers publish)
        if (t + 1 < T_STEPS) gemm_step(t + 1);
    }
}

// ---------------------------------------------------------------------------
extern "C" void kernel_launch(void* const* d_in, const int* in_sizes, int n_in,
                              void* d_out, int out_size) {
    const float* x  = (const float*)d_in[0];
    const float* W  = (const float*)d_in[1];
    const float* U  = (const float*)d_in[2];
    const float* b  = (const float*)d_in[3];
    const float* la = (const float*)d_in[4];
    float* out = (float*)d_out;

    prep_kernel<<<1, 512>>>(la);
    spacer_kernel<<<1, 32>>>();
    spacer_kernel<<<1, 32>>>();   // keep 4 launches/call: ncu slot 5 = lstm

    cudaFuncSetAttribute(lstm_kernel, cudaFuncAttributeMaxDynamicSharedMemorySize,
                         LSMEM_FLOATS * 4);
    lstm_kernel<<<NCTA, 256, LSMEM_FLOATS * 4>>>(x, U, W, b, out);
}

// round 13
// speedup vs baseline: 2.0315x; 1.4634x over previous
#include <cuda_runtime.h>
#include <cuda_bf16.h>
#include <math.h>
#include <stdint.h>

// Problem constants (fixed by dataset)
#define T_STEPS 2000
#define B_SZ    64
#define H_SZ    512
#define G4      2048
#define NCTA    128

typedef unsigned long long ull;

// ---------------------------------------------------------------------------
// Device scratch (no allocations allowed anywhere)
// ---------------------------------------------------------------------------
__device__ float        g_s[H_SZ];                   // gate vector s[H]
__device__ unsigned int g_flag[4 * 256];             // per (bg, ug) publish flags, 32B padded
__device__ float        g_h[4][B_SZ * H_SZ];         // h ring buffer (L2-resident)
__device__ float2       g_wp[256 * 2048];            // W transposed+k-paired: [kp][row]

// ---------------------------------------------------------------------------
// Packed f32x2 helpers (PTX-only)
// ---------------------------------------------------------------------------
__device__ __forceinline__ void fma2(ull& d, ull a, ull b) {
    asm("fma.rn.f32x2 %0, %1, %2, %0;" : "+l"(d) : "l"(a), "l"(b));
}
__device__ __forceinline__ void unpack2(ull v, float& x, float& y) {
    asm("mov.b64 {%0,%1}, %2;" : "=f"(x), "=f"(y) : "l"(v));
}
__device__ __forceinline__ ull pack2(float x, float y) {
    ull v;
    asm("mov.b64 %0, {%1,%2};" : "=l"(v) : "f"(x), "f"(y));
    return v;
}
__device__ __forceinline__ float sigf(float x) {
    return __fdividef(1.0f, 1.0f + __expf(-x));
}
// accurate fast tanh: (e^{2x}-1)/(e^{2x}+1), clamped (tanh saturates anyway)
__device__ __forceinline__ float tanhx(float x) {
    float xc = fminf(fmaxf(x, -15.0f), 15.0f);
    float e  = __expf(2.0f * xc);
    return __fdividef(e - 1.0f, e + 1.0f);
}

// ---------------------------------------------------------------------------
// Prep: s = clip(sigmoid(log_alpha)*1.2 - 0.1, 0, 1); zero h0; reset flags
// ---------------------------------------------------------------------------
__global__ void prep_kernel(const float* __restrict__ la) {
    int t = threadIdx.x;  // 512 threads
    float v = 1.0f / (1.0f + expf(-la[t]));
    v = v * 1.2f - 0.1f;
    v = fminf(fmaxf(v, 0.0f), 1.0f);
    g_s[t] = v;
    for (int i = t; i < B_SZ * H_SZ; i += 512) g_h[0][i] = 0.0f;
    if (t < 4 * 256) g_flag[t] = 0u;
}

// W transpose: g_wp[kp][row] = {W[row][2kp], W[row][2kp+1]}  (coalesced writes)
__global__ void prepw_kernel(const float* __restrict__ W) {
    int kp = blockIdx.x;                 // 0..255
    for (int row = threadIdx.x; row < 2048; row += blockDim.x) {
        g_wp[kp * 2048 + row] =
            make_float2(W[(size_t)row * 512 + 2 * kp],
                        W[(size_t)row * 512 + 2 * kp + 1]);
    }
}

// no-op spacer so the fixed `ncu -s 5 -c 1` lands on lstm_kernel
__global__ void spacer_kernel() { }

// ---------------------------------------------------------------------------
// Fused persistent kernel:
// 128 CTAs = 4 batch-groups (16 b) x 32 unit-groups (16 u).
// Per step: dot1 = h_t . U_hat (SMEM, mapping A); combine with gxr; publish;
// then dot2 = (x[t+1].s) . W_p (coalesced L2 stream, mapping B') -> gxr.
// Dataflow sync via per-(bg, ug) monotone flags; 4-deep h ring (skew-1 safe).
// ---------------------------------------------------------------------------
#define SHS 516                     // h/x row stride (16B-aligned rows)
#define SUS 516                     // U row stride
#define SRS 17                      // reduce buffer row stride
#define U_F   (64 * SUS)            // 33024
#define H_F   (16 * SHS)            // 8256
#define R_F   (8 * 64 * SRS)        // 8704
#define S_F   512
#define LSMEM_FLOATS (U_F + H_F + R_F + S_F + 32)

// ---- mapping A (dot1) --------------------------------------------------
#define LOADX(xv, kp)                                                           \
    do {                                                                        \
        _Pragma("unroll")                                                       \
        for (int bb = 0; bb < 4; ++bb)                                          \
            xv[bb] = *(const ulonglong2*)&h_s[(bb * 4 + bq) * SHS + kbase + 4 * (kp)]; \
    } while (0)

#define LOADU(uv, kp)                                                           \
    do {                                                                        \
        _Pragma("unroll")                                                       \
        for (int rr = 0; rr < 8; ++rr)                                          \
            uv[rr] = *(const ulonglong2*)&U_s[(rr * 8 + rq) * SUS + kbase + 4 * (kp)]; \
    } while (0)

#define FMASET(hv, uv)                                                          \
    do {                                                                        \
        _Pragma("unroll")                                                       \
        for (int bb = 0; bb < 4; ++bb)                                          \
            _Pragma("unroll")                                                   \
            for (int rr = 0; rr < 8; ++rr)                                      \
                fma2(acc[bb][rr], hv[bb].x, uv[rr].x);                          \
        _Pragma("unroll")                                                       \
        for (int bb = 0; bb < 4; ++bb)                                          \
            _Pragma("unroll")                                                   \
            for (int rr = 0; rr < 8; ++rr)                                      \
                fma2(acc[bb][rr], hv[bb].y, uv[rr].y);                          \
    } while (0)

#define REDWRITE()                                                              \
    do {                                                                        \
        _Pragma("unroll")                                                       \
        for (int bb = 0; bb < 4; ++bb)                                          \
            _Pragma("unroll")                                                   \
            for (int rr = 0; rr < 8; ++rr) {                                    \
                float x, y;                                                     \
                unpack2(acc[bb][rr], x, y);                                     \
                red[(warp * 64 + rr * 8 + rq) * SRS + bb * 4 + bq] = x + y;     \
            }                                                                   \
    } while (0)

// ---- mapping B' (gemm dot2): lane = (rq16, bq2); W from g_wp, coalesced ----
// 16 LDG.64 per 4-kp block; one line per (kp, rr) per warp.
#define LOADW16(wv, kb)                                                         \
    do {                                                                        \
        _Pragma("unroll")                                                       \
        for (int kpi = 0; kpi < 4; ++kpi)                                       \
            _Pragma("unroll")                                                   \
            for (int rr = 0; rr < 4; ++rr)                                      \
                wv[kpi * 4 + rr] = __ldg((const ull*)&g_wp[                     \
                    (size_t)(wkp0 + (kb) * 4 + kpi) * 2048 + rr * 512 + u0r]);  \
    } while (0)

#define REDWRITEB()                                                             \
    do {                                                                        \
        _Pragma("unroll")                                                       \
        for (int bb = 0; bb < 8; ++bb)                                          \
            _Pragma("unroll")                                                   \
            for (int rr = 0; rr < 4; ++rr) {                                    \
                float x, y;                                                     \
                unpack2(accg[bb][rr], x, y);                                    \
                red[(warp * 64 + rr * 16 + rq16) * SRS + bb * 2 + bq2] = x + y; \
            }                                                                   \
    } while (0)

__global__ void __launch_bounds__(256, 1)
lstm_kernel(const float* __restrict__ X, const float* __restrict__ U,
            const float* __restrict__ bias, float* __restrict__ out) {
    extern __shared__ float sm[];
    float* U_s = sm;
    float* h_s = sm + U_F;
    float* red = sm + U_F + H_F;
    float* s_s = sm + U_F + H_F + R_F;

    int tid  = threadIdx.x;
    int warp = tid >> 5;
    int lane = tid & 31;

    int ug = blockIdx.x >> 2;       // 0..31
    int bg = blockIdx.x & 3;        // 0..3
    int u0 = ug * 16;
    int b0 = bg * 16;

    unsigned int* myflag = &g_flag[bg * 256 + ug * 8];
    const unsigned int* wflag = &g_flag[bg * 256 + warp * 32 + (lane & 3) * 8];

    // ---- copy s to smem
    for (int i = tid; i < 512; i += 256) s_s[i] = g_s[i];

    // ---- load U_hat slice once: row lr = gate*16 + u_local
    for (int i = 0; i < 128; ++i) {
        int idx = i * 256 + tid;            // 0..32767
        int lr  = idx >> 9;
        int k   = idx & 511;
        int gg  = lr >> 4;
        int uu  = lr & 15;
        float v = U[((size_t)(gg * 512 + u0 + uu)) * 512 + k] * g_s[u0 + uu] * g_s[k];
        U_s[lr * SUS + k] = v;
    }

    // mapping A lane ids
    int rq    = lane & 7;
    int bq    = lane >> 3;
    int kbase = warp * 64;

    // mapping B' lane ids
    int rq16 = lane & 15;
    int bq2  = lane >> 4;
    int wkp0 = warp * 32;           // kp base of this warp's 64-k chunk
    int u0r  = u0 + rq16;

    // per-warp stage ids: lane covers b = lane&15, half = lane>>4
    int sb    = lane & 15;
    int shalf = lane >> 4;

    // combine-phase ids (one (b, u) cell per thread; u contiguous in lane)
    int cb = tid >> 4;              // 0..15
    int cu = tid & 15;              // 0..15
    float c_state = 0.0f;

    // per-thread bias (4 gates of cell (cb, cu))
    float bias_r[4];
#pragma unroll
    for (int g = 0; g < 4; ++g) bias_r[g] = bias[g * 512 + u0 + cu];

    float gxr[4];                   // gx for MY cell at the upcoming step

    __syncthreads();

    // ---- gemm for step tt -> gxr (stages x into h_s warp region; uses red)
    auto gemm_step = [&](int tt) {
        // stage x[tt] slice scaled by s (warp-private h_s column region)
        {
            const ull* src = (const ull*)(X + ((size_t)tt * 64 + b0) * 512);
#pragma unroll
            for (int j = 0; j < 16; ++j) {
                int c2 = warp * 32 + 2 * j + shalf;        // ull index in row
                ull v = __ldcg(&src[sb * 256 + c2]);
                float lo, hi;
                unpack2(v, lo, hi);
                lo *= s_s[2 * c2];
                hi *= s_s[2 * c2 + 1];
                *(ull*)&h_s[sb * SHS + kbase + 4 * j + 2 * shalf] = pack2(lo, hi);
            }
        }
        __syncwarp();

        ull accg[8][4];
#pragma unroll
        for (int i = 0; i < 8; ++i)
#pragma unroll
            for (int j = 0; j < 4; ++j) accg[i][j] = 0ull;

        {
            ull wva[16], wvb[16];
            LOADW16(wva, 0);
#pragma unroll
            for (int kb = 0; kb < 8; ++kb) {
                ull* wcur = (kb & 1) ? wvb : wva;
                ull* wnxt = (kb & 1) ? wva : wvb;
                if (kb < 7) {
                    if (kb & 1) { LOADW16(wva, kb + 1); }
                    else        { LOADW16(wvb, kb + 1); }
                }
                (void)wnxt;
#pragma unroll
                for (int kpi = 0; kpi < 4; ++kpi) {
                    ull xv[8];
#pragma unroll
                    for (int bb = 0; bb < 8; ++bb)
                        xv[bb] = *(const ull*)&h_s[(bb * 2 + bq2) * SHS +
                                                   kbase + 8 * kb + 2 * kpi];
#pragma unroll
                    for (int bb = 0; bb < 8; ++bb)
#pragma unroll
                        for (int rr = 0; rr < 4; ++rr)
                            fma2(accg[bb][rr], xv[bb], wcur[kpi * 4 + rr]);
                }
            }
        }

        REDWRITEB();
        __syncthreads();                       // S3: red2 ready

#pragma unroll
        for (int g = 0; g < 4; ++g) {
            float z = bias_r[g];
#pragma unroll
            for (int w = 0; w < 8; ++w)
                z += red[(w * 64 + g * 16 + cu) * SRS + cb];
            gxr[g] = z;
        }
        __syncthreads();                       // S4: red2 consumed
    };

    gemm_step(0);                              // gx for t = 0

    for (int t = 0; t < T_STEPS; ++t) {
        const float* hin  = g_h[t & 3];
        float*       hout = g_h[(t + 1) & 3];

        // ---- wait for this warp's 4 producer unit-groups (h_t published)
        {
            unsigned v;
            do {
                asm volatile("ld.relaxed.gpu.u32 %0, [%1];"
                             : "=r"(v) : "l"(wflag));
            } while (__any_sync(0xffffffffu, (int)v < t));
            asm volatile("fence.acquire.gpu;" ::: "memory");
        }

        // ---- per-warp h stage: this warp's 16 b x 64 k slice (4 KB), CF banks
        {
            const ull* src = (const ull*)(hin + (size_t)b0 * 512);
#pragma unroll
            for (int j = 0; j < 16; ++j) {
                ull v = __ldcg(&src[sb * 256 + warp * 32 + 2 * j + shalf]);
                *(ull*)&h_s[sb * SHS + kbase + 4 * j + 2 * shalf] = v;
            }
        }
        __syncwarp();

        // ---- dot1: h . U_hat (2-stage pipelined, x/y-split FMA passes)
        ull acc[4][8];
#pragma unroll
        for (int i = 0; i < 4; ++i)
#pragma unroll
            for (int j = 0; j < 8; ++j) acc[i][j] = 0ull;

        {
            ulonglong2 hva[4], uva[8], hvb[4], uvb[8];
            LOADX(hva, 0);
            LOADU(uva, 0);
#pragma unroll
            for (int kp2 = 0; kp2 < 8; ++kp2) {
                LOADX(hvb, 2 * kp2 + 1);
                LOADU(uvb, 2 * kp2 + 1);
                FMASET(hva, uva);
                if (kp2 < 7) {
                    LOADX(hva, 2 * kp2 + 2);
                    LOADU(uva, 2 * kp2 + 2);
                }
                FMASET(hvb, uvb);
            }
        }

        REDWRITE();
        __syncthreads();                       // S1: red1 ready

        // ---- fused reduce + combine: one (b, u) cell per thread
        float z0 = gxr[0], z1 = gxr[1], z2 = gxr[2], z3 = gxr[3];
#pragma unroll
        for (int w = 0; w < 8; ++w) {
            z0 += red[(w * 64 +  0 + cu) * SRS + cb];
            z1 += red[(w * 64 + 16 + cu) * SRS + cb];
            z2 += red[(w * 64 + 32 + cu) * SRS + cb];
            z3 += red[(w * 64 + 48 + cu) * SRS + cb];
        }
        float ig = sigf(z0);
        float fg = sigf(z1);
        float gg = tanhx(z2);
        float og = sigf(z3);
        float cn = fg * c_state + ig * gg;
        c_state  = cn;
        float hn = og * tanhx(cn);

        // h exchange store (L2) must precede the publish
        hout[(b0 + cb) * 512 + u0 + cu] = hn;

        __syncthreads();                       // S2: hout stores + red1 reads done
        if (tid == 0) {
            asm volatile("fence.acq_rel.gpu;" ::: "memory");
            asm volatile("st.release.gpu.u32 [%0], %1;"
                         :: "l"(myflag), "r"(t + 1) : "memory");
        }

        // DRAM output store overlaps peers' publication
        out[((size_t)t * 64 + b0 + cb) * 512 + u0 + cu] = hn;

        // ---- gemm for step t+1 (fills idle pipes while peers publish)
        if (t + 1 < T_STEPS) gemm_step(t + 1);
    }
}

// ---------------------------------------------------------------------------
extern "C" void kernel_launch(void* const* d_in, const int* in_sizes, int n_in,
                              void* d_out, int out_size) {
    const float* x  = (const float*)d_in[0];
    const float* W  = (const float*)d_in[1];
    const float* U  = (const float*)d_in[2];
    const float* b  = (const float*)d_in[3];
    const float* la = (const float*)d_in[4];
    float* out = (float*)d_out;

    prep_kernel<<<1, 512>>>(la);
    prepw_kernel<<<256, 512>>>(W);
    spacer_kernel<<<1, 32>>>();   // keep 4 launches/call: ncu slot 5 = lstm

    cudaFuncSetAttribute(lstm_kernel, cudaFuncAttributeMaxDynamicSharedMemorySize,
                         LSMEM_FLOATS * 4);
    lstm_kernel<<<NCTA, 256, LSMEM_FLOATS * 4>>>(x, U, b, out);
}

// round 15
// speedup vs baseline: 3.3052x; 1.6270x over previous
#include <cuda_runtime.h>
#include <cuda_bf16.h>
#include <math.h>
#include <stdint.h>

// Problem constants (fixed by dataset)
#define T_STEPS 2000
#define B_SZ    64
#define H_SZ    512
#define NCTA    128

typedef unsigned long long ull;

// ---------------------------------------------------------------------------
// Device scratch (no allocations allowed anywhere)
// ---------------------------------------------------------------------------
__device__ float        g_s[H_SZ];                   // gate vector s[H]
__device__ unsigned int g_flag[4 * 256];             // per (bg, ug) publish flags, 32B padded
__device__ float        g_h[4][B_SZ * H_SZ];         // h ring buffer (L2-resident)
__device__ float2       g_wp[256 * 2048];            // W transposed+k-paired: [kp][row]

// ---------------------------------------------------------------------------
// Packed f32x2 helpers (PTX-only)
// ---------------------------------------------------------------------------
__device__ __forceinline__ void fma2(ull& d, ull a, ull b) {
    asm("fma.rn.f32x2 %0, %1, %2, %0;" : "+l"(d) : "l"(a), "l"(b));
}
__device__ __forceinline__ void unpack2(ull v, float& x, float& y) {
    asm("mov.b64 {%0,%1}, %2;" : "=f"(x), "=f"(y) : "l"(v));
}
__device__ __forceinline__ float sigf(float x) {
    return __fdividef(1.0f, 1.0f + __expf(-x));
}
__device__ __forceinline__ float tanhx(float x) {
    float xc = fminf(fmaxf(x, -15.0f), 15.0f);
    float e  = __expf(2.0f * xc);
    return __fdividef(e - 1.0f, e + 1.0f);
}

// ---------------------------------------------------------------------------
// Prep kernels
// ---------------------------------------------------------------------------
__global__ void prep_kernel(const float* __restrict__ la) {
    int t = threadIdx.x;  // 512 threads
    float v = 1.0f / (1.0f + expf(-la[t]));
    v = v * 1.2f - 0.1f;
    v = fminf(fmaxf(v, 0.0f), 1.0f);
    g_s[t] = v;
    for (int i = t; i < B_SZ * H_SZ; i += 512) g_h[0][i] = 0.0f;
    if (t < 4 * 256) g_flag[t] = 0u;
}

// W transpose: g_wp[kp][row] = {W[row][2kp], W[row][2kp+1]}
__global__ void prepw_kernel(const float* __restrict__ W) {
    int kp = blockIdx.x;                 // 0..255
    for (int row = threadIdx.x; row < 2048; row += blockDim.x) {
        g_wp[kp * 2048 + row] =
            make_float2(W[(size_t)row * 512 + 2 * kp],
                        W[(size_t)row * 512 + 2 * kp + 1]);
    }
}

// no-op spacer so the fixed `ncu -s 5 -c 1` lands on lstm_kernel
__global__ void spacer_kernel() { }

// ---------------------------------------------------------------------------
// Warp-specialized fused persistent kernel:
// 128 CTAs = 4 batch-groups (16 b) x 32 unit-groups (16 u), 8 warps.
// Warps 0-3: recurrent dot (h_t . U_hat), 128-k chunk each, U in SMEM.
// Warps 4-7: x-GEMM for step t+1 ((x.s) . W), W streamed coalesced from L2.
// red buffer time-shared between groups; gx via double-buffered smem.
// Dataflow sync via per-(bg, ug) monotone flags; 4-deep h ring (skew-1 safe).
// ---------------------------------------------------------------------------
#define SHS 516                     // h/x row stride (16B-aligned rows)
#define SUS 516                     // U row stride
#define SRS 17                      // reduce buffer row stride
#define U_F   (64 * SUS)            // 33024
#define H_F   (16 * SHS)            // 8256
#define X_F   (16 * SHS)            // 8256
#define R_F   (4 * 64 * SRS)        // 4352
#define GX_F  2048                  // gx double buffer [2][64*16]
#define S_F   512
#define B_F   64
#define LSMEM_FLOATS (U_F + H_F + X_F + R_F + GX_F + S_F + B_F + 32)  // 56544

// ---- dot (mapping A): lane = (rq 8-row-slot, bq 4-batch-slot) ----------
#define LOADX(xv, kp)                                                           \
    do {                                                                        \
        _Pragma("unroll")                                                       \
        for (int bb = 0; bb < 4; ++bb)                                          \
            xv[bb] = *(const ulonglong2*)&h_s[(bb * 4 + bq) * SHS + kbase + 4 * (kp)]; \
    } while (0)

#define LOADU(uv, kp)                                                           \
    do {                                                                        \
        _Pragma("unroll")                                                       \
        for (int rr = 0; rr < 8; ++rr)                                          \
            uv[rr] = *(const ulonglong2*)&U_s[(rr * 8 + rq) * SUS + kbase + 4 * (kp)]; \
    } while (0)

#define FMASET(hv, uv)                                                          \
    do {                                                                        \
        _Pragma("unroll")                                                       \
        for (int bb = 0; bb < 4; ++bb)                                          \
            _Pragma("unroll")                                                   \
            for (int rr = 0; rr < 8; ++rr)                                      \
                fma2(acc[bb][rr], hv[bb].x, uv[rr].x);                          \
        _Pragma("unroll")                                                       \
        for (int bb = 0; bb < 4; ++bb)                                          \
            _Pragma("unroll")                                                   \
            for (int rr = 0; rr < 8; ++rr)                                      \
                fma2(acc[bb][rr], hv[bb].y, uv[rr].y);                          \
    } while (0)

// ---- gemm (mapping B): lane = (rq16 row-slot, bq2 batch-slot) ----------
#define LOADW16(wv, kb)                                                         \
    do {                                                                        \
        _Pragma("unroll")                                                       \
        for (int kpi = 0; kpi < 4; ++kpi)                                       \
            _Pragma("unroll")                                                   \
            for (int rr = 0; rr < 4; ++rr)                                      \
                wv[kpi * 4 + rr] = __ldg((const ull*)&g_wp[                     \
                    (size_t)(wkp0 + (kb) * 4 + kpi) * 2048 + rr * 512 + u0r]);  \
    } while (0)

#define GEMM4(wv, kb)                                                           \
    do {                                                                        \
        _Pragma("unroll")                                                       \
        for (int kpi = 0; kpi < 4; ++kpi) {                                     \
            int gk = (kb) * 4 + kpi;                                            \
            ull xv[8];                                                          \
            _Pragma("unroll")                                                   \
            for (int bb = 0; bb < 8; ++bb)                                      \
                xv[bb] = *(const ull*)&x_s[(bb * 2 + bq2) * SHS + kbase + 2 * gk]; \
            _Pragma("unroll")                                                   \
            for (int bb = 0; bb < 8; ++bb)                                      \
                _Pragma("unroll")                                               \
                for (int rr = 0; rr < 4; ++rr)                                  \
                    fma2(accg[bb][rr], xv[bb], wv[kpi * 4 + rr]);               \
        }                                                                       \
    } while (0)

__global__ void __launch_bounds__(256, 1)
lstm_kernel(const float* __restrict__ X, const float* __restrict__ U,
            const float* __restrict__ bias, float* __restrict__ out) {
    extern __shared__ float sm[];
    float* U_s  = sm;
    float* h_s  = sm + U_F;
    float* x_s  = sm + U_F + H_F;
    float* red  = sm + U_F + H_F + X_F;
    float* gx_s = sm + U_F + H_F + X_F + R_F;           // [2][1024]
    float* s_s  = sm + U_F + H_F + X_F + R_F + GX_F;
    float* b_s  = sm + U_F + H_F + X_F + R_F + GX_F + S_F;

    int tid  = threadIdx.x;
    int warp = tid >> 5;
    int lane = tid & 31;

    int ug = blockIdx.x >> 2;       // 0..31
    int bg = blockIdx.x & 3;        // 0..3
    int u0 = ug * 16;
    int b0 = bg * 16;

    unsigned int* myflag = &g_flag[bg * 256 + ug * 8];

    // ---- stage s and row-mapped bias (row = gate*16 + u_local)
    for (int i = tid; i < 512; i += 256) s_s[i] = g_s[i];
    if (tid < 64) b_s[tid] = bias[(tid >> 4) * 512 + u0 + (tid & 15)];

    // ---- load U_hat slice once: row lr = gate*16 + u_local
    for (int i = 0; i < 128; ++i) {
        int idx = i * 256 + tid;            // 0..32767
        int lr  = idx >> 9;
        int k   = idx & 511;
        int gg  = lr >> 4;
        int uu  = lr & 15;
        float v = U[((size_t)(gg * 512 + u0 + uu)) * 512 + k] * g_s[u0 + uu] * g_s[k];
        U_s[lr * SUS + k] = v;
    }
    __syncthreads();

    bool dotg = (warp < 4);

    if (dotg) {
        // ===================== DOT GROUP (warps 0-3) =====================
        int rq    = lane & 7;
        int bq    = lane >> 3;
        int kbase = warp * 128;
        const unsigned int* wflag =
            &g_flag[bg * 256 + (warp * 8 + (lane & 7)) * 8];

        int cu  = tid & 15;                // unit
        int cb0 = tid >> 4;                // batch 0..7 (also handles cb0+8)
        float c0 = 0.0f, c1 = 0.0f;

        __syncthreads();                   // matches gemm prologue barrier

        for (int t = 0; t < T_STEPS; ++t) {
            const float* hin  = g_h[t & 3];
            float*       hout = g_h[(t + 1) & 3];

            // wait for the 8 producer unit-groups of this warp's k-chunk
            {
                unsigned v;
                do {
                    asm volatile("ld.relaxed.gpu.u32 %0, [%1];"
                                 : "=r"(v) : "l"(wflag));
                } while (__any_sync(0xffffffffu, (int)v < t));
                asm volatile("fence.acquire.gpu;" ::: "memory");
            }

            // stage this warp's 16 b x 128 k slice (float4 coalesced)
            {
#pragma unroll
                for (int b = 0; b < 16; ++b) {
                    float4 v = __ldcg((const float4*)&hin[(b0 + b) * 512 + kbase] + lane);
                    *(float4*)&h_s[b * SHS + kbase + 4 * lane] = v;
                }
            }
            __syncwarp();

            // dot1: 32 kpi, 2-stage pipeline, x/y-split passes
            ull acc[4][8];
#pragma unroll
            for (int i = 0; i < 4; ++i)
#pragma unroll
                for (int j = 0; j < 8; ++j) acc[i][j] = 0ull;
            {
                ulonglong2 hva[4], uva[8], hvb[4], uvb[8];
                LOADX(hva, 0);
                LOADU(uva, 0);
#pragma unroll
                for (int kp2 = 0; kp2 < 16; ++kp2) {
                    LOADX(hvb, 2 * kp2 + 1);
                    LOADU(uvb, 2 * kp2 + 1);
                    FMASET(hva, uva);
                    if (kp2 < 15) {
                        LOADX(hva, 2 * kp2 + 2);
                        LOADU(uva, 2 * kp2 + 2);
                    }
                    FMASET(hvb, uvb);
                }
            }

            __syncthreads();               // S1: red free
#pragma unroll
            for (int bb = 0; bb < 4; ++bb)
#pragma unroll
                for (int rr = 0; rr < 8; ++rr) {
                    float x, y;
                    unpack2(acc[bb][rr], x, y);
                    red[(warp * 64 + rr * 8 + rq) * SRS + bb * 4 + bq] = x + y;
                }
            __syncthreads();               // S2: red complete

            // combine: two cells (cb0, cu) and (cb0+8, cu)
            const float* gxb = gx_s + (t & 1) * 1024;
            float hn0, hn1;
            {
                float z0 = gxb[( 0 + cu) * 16 + cb0];
                float z1 = gxb[(16 + cu) * 16 + cb0];
                float z2 = gxb[(32 + cu) * 16 + cb0];
                float z3 = gxb[(48 + cu) * 16 + cb0];
#pragma unroll
                for (int w = 0; w < 4; ++w) {
                    z0 += red[(w * 64 +  0 + cu) * SRS + cb0];
                    z1 += red[(w * 64 + 16 + cu) * SRS + cb0];
                    z2 += red[(w * 64 + 32 + cu) * SRS + cb0];
                    z3 += red[(w * 64 + 48 + cu) * SRS + cb0];
                }
                float cn = sigf(z1) * c0 + sigf(z0) * tanhx(z2);
                c0 = cn;
                hn0 = sigf(z3) * tanhx(cn);
                hout[(b0 + cb0) * 512 + u0 + cu] = hn0;
            }
            {
                int cb = cb0 + 8;
                float z0 = gxb[( 0 + cu) * 16 + cb];
                float z1 = gxb[(16 + cu) * 16 + cb];
                float z2 = gxb[(32 + cu) * 16 + cb];
                float z3 = gxb[(48 + cu) * 16 + cb];
#pragma unroll
                for (int w = 0; w < 4; ++w) {
                    z0 += red[(w * 64 +  0 + cu) * SRS + cb];
                    z1 += red[(w * 64 + 16 + cu) * SRS + cb];
                    z2 += red[(w * 64 + 32 + cu) * SRS + cb];
                    z3 += red[(w * 64 + 48 + cu) * SRS + cb];
                }
                float cn = sigf(z1) * c1 + sigf(z0) * tanhx(z2);
                c1 = cn;
                hn1 = sigf(z3) * tanhx(cn);
                hout[(b0 + cb) * 512 + u0 + cu] = hn1;
            }

            __syncthreads();               // S3: hout + red reads done
            if (tid == 0) {
                asm volatile("fence.acq_rel.gpu;" ::: "memory");
                asm volatile("st.release.gpu.u32 [%0], %1;"
                             :: "l"(myflag), "r"(t + 1) : "memory");
            }
            out[((size_t)t * 64 + b0 + cb0) * 512 + u0 + cu] = hn0;
            out[((size_t)t * 64 + b0 + cb0 + 8) * 512 + u0 + cu] = hn1;
        }
    } else {
        // ===================== GEMM GROUP (warps 4-7) =====================
        int wg    = warp - 4;
        int kbase = wg * 128;
        int wkp0  = wg * 64;
        int rq16  = lane & 15;
        int bq2   = lane >> 4;
        int u0r   = u0 + rq16;
        int gtid  = tid - 128;             // 0..127

        // per-lane s quad for x staging (constant across steps)
        float4 ss4 = *(const float4*)&s_s[kbase + 4 * lane];

        // gemm for step tt: stage x, dot2, red-reduce into gx_s[tt&1]
        auto gemm_work = [&](int tt) {
            // stage (x[tt].s): float4 coalesced, warp-private columns
#pragma unroll
            for (int b = 0; b < 16; ++b) {
                float4 v = __ldcg((const float4*)&X[((size_t)tt * 64 + b0 + b) * 512 + kbase] + lane);
                v.x *= ss4.x; v.y *= ss4.y; v.z *= ss4.z; v.w *= ss4.w;
                *(float4*)&x_s[b * SHS + kbase + 4 * lane] = v;
            }
            __syncwarp();

            ull accg[8][4];
#pragma unroll
            for (int i = 0; i < 8; ++i)
#pragma unroll
                for (int j = 0; j < 4; ++j) accg[i][j] = 0ull;
            {
                ull wva[16], wvb[16];
                LOADW16(wva, 0);
#pragma unroll
                for (int kb2 = 0; kb2 < 8; ++kb2) {
                    LOADW16(wvb, 2 * kb2 + 1);
                    GEMM4(wva, 2 * kb2);
                    if (kb2 < 7) LOADW16(wva, 2 * kb2 + 2);
                    GEMM4(wvb, 2 * kb2 + 1);
                }
            }

            // partials -> red (red is free in this phase)
#pragma unroll
            for (int bb = 0; bb < 8; ++bb)
#pragma unroll
                for (int rr = 0; rr < 4; ++rr) {
                    float x, y;
                    unpack2(accg[bb][rr], x, y);
                    red[(wg * 64 + rr * 16 + rq16) * SRS + bb * 2 + bq2] = x + y;
                }
            asm volatile("bar.sync 2, 128;" ::: "memory");

            // reduce 4 warp-slots -> gx_s[tt&1], bias folded in
            float* gxo = gx_s + (tt & 1) * 1024;
#pragma unroll
            for (int i = 0; i < 8; ++i) {
                int e   = gtid * 8 + i;        // 0..1023
                int row = e >> 4;
                int b   = e & 15;
                float z = b_s[row];
#pragma unroll
                for (int w = 0; w < 4; ++w)
                    z += red[(w * 64 + row) * SRS + b];
                gxo[row * 16 + b] = z;
            }
        };

        gemm_work(0);                      // gx for t = 0 (red untouched by dot yet)
        __syncthreads();                   // matches dot group's pre-loop barrier

        for (int t = 0; t < T_STEPS; ++t) {
            // region P: compute dot2 for t+1 into accg (kept in a local scope
            // inside gemm_work's second half below, split around the syncs)
            bool work = (t + 1 < T_STEPS);
            ull accg[8][4];
            if (work) {
#pragma unroll
                for (int b = 0; b < 16; ++b) {
                    float4 v = __ldcg((const float4*)&X[((size_t)(t + 1) * 64 + b0 + b) * 512 + kbase] + lane);
                    v.x *= ss4.x; v.y *= ss4.y; v.z *= ss4.z; v.w *= ss4.w;
                    *(float4*)&x_s[b * SHS + kbase + 4 * lane] = v;
                }
                __syncwarp();
#pragma unroll
                for (int i = 0; i < 8; ++i)
#pragma unroll
                    for (int j = 0; j < 4; ++j) accg[i][j] = 0ull;
                {
                    ull wva[16], wvb[16];
                    LOADW16(wva, 0);
#pragma unroll
                    for (int kb2 = 0; kb2 < 8; ++kb2) {
                        LOADW16(wvb, 2 * kb2 + 1);
                        GEMM4(wva, 2 * kb2);
                        if (kb2 < 7) LOADW16(wva, 2 * kb2 + 2);
                        GEMM4(wvb, 2 * kb2 + 1);
                    }
                }
            }

            __syncthreads();               // S1
            __syncthreads();               // S2
            __syncthreads();               // S3: dot group done with red

            if (work) {
#pragma unroll
                for (int bb = 0; bb < 8; ++bb)
#pragma unroll
                    for (int rr = 0; rr < 4; ++rr) {
                        float x, y;
                        unpack2(accg[bb][rr], x, y);
                        red[(wg * 64 + rr * 16 + rq16) * SRS + bb * 2 + bq2] = x + y;
                    }
                asm volatile("bar.sync 2, 128;" ::: "memory");

                float* gxo = gx_s + ((t + 1) & 1) * 1024;
#pragma unroll
                for (int i = 0; i < 8; ++i) {
                    int e   = gtid * 8 + i;
                    int row = e >> 4;
                    int b   = e & 15;
                    float z = b_s[row];
#pragma unroll
                    for (int w = 0; w < 4; ++w)
                        z += red[(w * 64 + row) * SRS + b];
                    gxo[row * 16 + b] = z;
                }
            }
        }
    }
}

// ---------------------------------------------------------------------------
extern "C" void kernel_launch(void* const* d_in, const int* in_sizes, int n_in,
                              void* d_out, int out_size) {
    const float* x  = (const float*)d_in[0];
    const float* W  = (const float*)d_in[1];
    const float* U  = (const float*)d_in[2];
    const float* b  = (const float*)d_in[3];
    const float* la = (const float*)d_in[4];
    float* out = (float*)d_out;

    prep_kernel<<<1, 512>>>(la);
    prepw_kernel<<<256, 512>>>(W);
    spacer_kernel<<<1, 32>>>();   // keep 4 launches/call: ncu slot 5 = lstm

    cudaFuncSetAttribute(lstm_kernel, cudaFuncAttributeMaxDynamicSharedMemorySize,
                         LSMEM_FLOATS * 4);
    lstm_kernel<<<NCTA, 256, LSMEM_FLOATS * 4>>>(x, U, b, out);
}